// round 1
// baseline (speedup 1.0000x reference)
#include <cuda_runtime.h>
#include <math.h>

// Problem constants (fixed by setup_inputs)
#define BB 32
#define HH 512
#define WW 512
#define HW (HH * WW)          // 262144
#define NPIX (BB * HW)        // 8388608
#define VV 64
#define V3 (VV * VV * VV)     // 262144
#define NVOX (BB * V3)        // 8388608

// Accumulator: .x = count, .y/.z/.w = r/g/b sums. AoS so one splat touches one
// 16B group (single 32B sector) -> best atomic locality. 128 MB static scratch.
__device__ float4 g_acc[NVOX];

__global__ void zero_acc_kernel() {
    int i = blockIdx.x * blockDim.x + threadIdx.x;
    if (i < NVOX) g_acc[i] = make_float4(0.f, 0.f, 0.f, 0.f);
}

__global__ void splat_kernel(const float* __restrict__ rgbd) {
    int idx = blockIdx.x * blockDim.x + threadIdx.x;
    if (idx >= NPIX) return;

    int b = idx >> 18;          // / HW
    int p = idx & (HW - 1);     // % HW
    int h = p >> 9;             // / WW
    int w = p & (WW - 1);       // % WW

    const float* base = rgbd + (size_t)b * 4 * HW;
    float d = base[3 * HW + p];                 // coalesced depth-plane read

    // depth_valid = (d>0) & (d<10) & isfinite(d)
    if (!(d > 0.0f && d < 10.0f && isfinite(d))) return;

    // fx=fy=256, cx=cy=256
    float x = ((float)w - 256.0f) * d * (1.0f / 256.0f);
    float y = ((float)h - 256.0f) * d * (1.0f / 256.0f);

    // coords = round((p - SMIN)/(SMAX-SMIN) * (V-1)) = rint((p+2)*15.75)
    // rintf = round-half-even, matches jnp.round. 15.75 == 63/4 exactly, so
    // this has the same single rounding as ((p+2)/4)*63 in the reference.
    float fx_ = rintf((x + 2.0f) * 15.75f);
    float fy_ = rintf((y + 2.0f) * 15.75f);
    float fz_ = rintf((d + 2.0f) * 15.75f);

    if (fx_ < 0.0f || fx_ > 63.0f) return;
    if (fy_ < 0.0f || fy_ > 63.0f) return;
    if (fz_ < 0.0f || fz_ > 63.0f) return;

    int cx = (int)fx_, cy = (int)fy_, cz = (int)fz_;
    int lin = (((b << 6) + cx) << 6 | cy) << 6 | cz;  // ((b*64+cx)*64+cy)*64+cz

    float r = base[0 * HW + p];
    float g = base[1 * HW + p];
    float bl = base[2 * HW + p];

    float* a = (float*)&g_acc[lin];
    atomicAdd(a + 0, 1.0f);
    atomicAdd(a + 1, r);
    atomicAdd(a + 2, g);
    atomicAdd(a + 3, bl);
}

__global__ void finalize_kernel(float* __restrict__ out) {
    int i = blockIdx.x * blockDim.x + threadIdx.x;
    if (i >= NVOX) return;

    int b = i >> 18;            // / V3
    int r = i & (V3 - 1);       // % V3

    float4 a = g_acc[i];
    float* ob = out + (size_t)b * 4 * V3;

    if (a.x > 0.0f) {
        ob[r]          = 1.0f;
        ob[V3 + r]     = a.y / a.x;   // max(count,1)==count when count>0
        ob[2 * V3 + r] = a.z / a.x;
        ob[3 * V3 + r] = a.w / a.x;
    } else {
        ob[r]          = 0.0f;
        ob[V3 + r]     = 0.0f;
        ob[2 * V3 + r] = 0.0f;
        ob[3 * V3 + r] = 0.0f;
    }
}

extern "C" void kernel_launch(void* const* d_in, const int* in_sizes, int n_in,
                              void* d_out, int out_size) {
    const float* rgbd = (const float*)d_in[0];
    float* out = (float*)d_out;

    const int T = 256;
    zero_acc_kernel<<<(NVOX + T - 1) / T, T>>>();
    splat_kernel<<<(NPIX + T - 1) / T, T>>>(rgbd);
    finalize_kernel<<<(NVOX + T - 1) / T, T>>>(out);
}

// round 2
// speedup vs baseline: 1.2246x; 1.2246x over previous
#include <cuda_runtime.h>
#include <math.h>

// Problem constants (fixed by setup_inputs)
#define HH 512
#define WW 512
#define HW (HH * WW)          // 262144
#define NPIX (32 * HW)        // 8388608
#define VV 64
#define V3 (VV * VV * VV)     // 262144
#define NVOX (32 * V3)        // 8388608

// Reachability: d>0 && d<10 && coords in range forces cz = rint((d+2)*15.75)
// in [32,63] (d+2 >= 2.0 in fp32, 2.0*15.75 = 31.5 -> rint -> 32; upper bound
// from cz <= 63 check). So only half the z-range ever accumulates.
// Scratch layout: [((b*64+cx)*64+cy)*32 + (cz-32)] of float4{count, r, g, b}.
#define NSCRATCH (NVOX / 2)   // 4194304 * 16B = 64 MB

__device__ float4 g_acc[NSCRATCH];   // zero-initialized at module load;
                                     // finalize re-zeros it each call.

__global__ void splat_kernel(const float* __restrict__ rgbd) {
    int t = blockIdx.x * blockDim.x + threadIdx.x;
    if (t >= NPIX / 4) return;
    int idx = t << 2;                // first of 4 consecutive pixels
    int b = idx >> 18;               // / HW
    int p = idx & (HW - 1);          // % HW   (multiple of 4)
    int h = p >> 9;                  // row (same for all 4: 512 % 4 == 0)
    int w0 = p & (WW - 1);

    const float* base = rgbd + (size_t)b * (4 * HW);
    float4 d4 = *(const float4*)(base + 3 * HW + p);

    float dv[4] = {d4.x, d4.y, d4.z, d4.w};
    int   lin[4];
    bool  valid[4];
    bool  any = false;
    float yb = (float)h - 256.0f;    // fx=fy=256, cx=cy=256

    #pragma unroll
    for (int k = 0; k < 4; k++) {
        float d = dv[k];
        bool ok = (d > 0.0f) && (d < 10.0f) && isfinite(d);
        float x = ((float)(w0 + k) - 256.0f) * d * (1.0f / 256.0f);
        float y = yb * d * (1.0f / 256.0f);
        // rintf = round-half-even = jnp.round; 15.75 == 63/4 exactly, same
        // single rounding as ((p+2)/4)*63 in the reference.
        float fx_ = rintf((x + 2.0f) * 15.75f);
        float fy_ = rintf((y + 2.0f) * 15.75f);
        float fz_ = rintf((d + 2.0f) * 15.75f);
        ok = ok && (fx_ >= 0.0f) && (fx_ <= 63.0f)
                && (fy_ >= 0.0f) && (fy_ <= 63.0f)
                && (fz_ >= 32.0f) && (fz_ <= 63.0f);  // fz<32 impossible when d>0
        valid[k] = ok;
        any = any || ok;
        int cx = (int)fx_, cy = (int)fy_, cz = (int)fz_;
        lin[k] = ((((b << 6) + cx) << 6) | cy) << 5 | (cz - 32);
    }

    if (!any) return;   // ~32% of threads skip the RGB loads entirely

    float4 r4 = *(const float4*)(base + 0 * HW + p);
    float4 g4 = *(const float4*)(base + 1 * HW + p);
    float4 b4 = *(const float4*)(base + 2 * HW + p);
    float rv[4] = {r4.x, r4.y, r4.z, r4.w};
    float gv[4] = {g4.x, g4.y, g4.z, g4.w};
    float bv[4] = {b4.x, b4.y, b4.z, b4.w};

    #pragma unroll
    for (int k = 0; k < 4; k++) {
        if (valid[k]) {
            float* a = (float*)&g_acc[lin[k]];
            // One 128-bit vector reduction instead of 4 scalar atomics (sm_90+).
            asm volatile(
                "red.global.add.v4.f32 [%0], {%1, %2, %3, %4};"
                :: "l"(a), "f"(1.0f), "f"(rv[k]), "f"(gv[k]), "f"(bv[k])
                : "memory");
        }
    }
}

__device__ __forceinline__ void resolve(float4 a, float& occ, float& r,
                                        float& g, float& b) {
    if (a.x > 0.0f) {
        occ = 1.0f;
        r = a.y / a.x;   // max(count,1)==count when count>0
        g = a.z / a.x;
        b = a.w / a.x;
    } else {
        occ = r = g = b = 0.0f;
    }
}

__global__ void finalize_kernel(float* __restrict__ out) {
    int t = blockIdx.x * blockDim.x + threadIdx.x;
    if (t >= NVOX / 4) return;
    int i4 = t << 2;                 // 4 consecutive voxels (cz fastest)
    int b = i4 >> 18;                // / V3
    int r0 = i4 & (V3 - 1);          // % V3   (multiple of 4)

    float* ob = out + (size_t)b * (4 * V3) + r0;
    float4 occ, rr, gg, bb;

    if ((r0 & 32) == 0) {
        // cz in [0,32): never accumulated -> all zeros, no scratch traffic.
        occ = rr = gg = bb = make_float4(0.f, 0.f, 0.f, 0.f);
    } else {
        // cz-32 = (i4 & 31) here; scratch indices are contiguous for the 4.
        int s = (i4 >> 6) * 32 + (i4 & 31);
        float4 a0 = g_acc[s + 0];
        float4 a1 = g_acc[s + 1];
        float4 a2 = g_acc[s + 2];
        float4 a3 = g_acc[s + 3];
        // Re-zero scratch for the next call (graph replays reuse it).
        float4 z = make_float4(0.f, 0.f, 0.f, 0.f);
        g_acc[s + 0] = z; g_acc[s + 1] = z; g_acc[s + 2] = z; g_acc[s + 3] = z;

        resolve(a0, occ.x, rr.x, gg.x, bb.x);
        resolve(a1, occ.y, rr.y, gg.y, bb.y);
        resolve(a2, occ.z, rr.z, gg.z, bb.z);
        resolve(a3, occ.w, rr.w, gg.w, bb.w);
    }

    *(float4*)(ob)          = occ;
    *(float4*)(ob + V3)     = rr;
    *(float4*)(ob + 2 * V3) = gg;
    *(float4*)(ob + 3 * V3) = bb;
}

extern "C" void kernel_launch(void* const* d_in, const int* in_sizes, int n_in,
                              void* d_out, int out_size) {
    const float* rgbd = (const float*)d_in[0];
    float* out = (float*)d_out;

    const int T = 256;
    splat_kernel<<<(NPIX / 4 + T - 1) / T, T>>>(rgbd);
    finalize_kernel<<<(NVOX / 4 + T - 1) / T, T>>>(out);
}

// round 3
// speedup vs baseline: 1.5895x; 1.2980x over previous
#include <cuda_runtime.h>
#include <math.h>

// Problem constants (fixed by setup_inputs)
#define HH 512
#define WW 512
#define HW (HH * WW)          // 262144
#define NPIX (32 * HW)        // 8388608
#define VV 64
#define V3 (VV * VV * VV)     // 262144
#define NVOX (32 * V3)        // 8388608

// Reachability: d>0 && coords in range forces cz = rint((d+2)*15.75) in
// [32,63] (d+2 >= 2.0 in fp32 and 2.0*15.75 = 31.5 ->rint-> 32).
// Scratch layout: [((b*64+cx)*64+cy)*32 + (cz-32)] of float4{count, r, g, b}.
#define NSCRATCH (NVOX / 2)        // 4194304 entries * 16B = 64 MB
#define SCR_PER_B (VV * VV * 32)   // 131072

__device__ float4 g_acc[NSCRATCH];   // zero-init at load; finalize re-zeros.

__global__ void splat_kernel(const float* __restrict__ rgbd) {
    int t = blockIdx.x * blockDim.x + threadIdx.x;
    if (t >= NPIX / 4) return;
    int idx = t << 2;                // first of 4 consecutive pixels
    int b = idx >> 18;               // / HW
    int p = idx & (HW - 1);          // % HW   (multiple of 4)
    int h = p >> 9;                  // row (same for all 4: 512 % 4 == 0)
    int w0 = p & (WW - 1);

    const float* base = rgbd + (size_t)b * (4 * HW);
    float4 d4 = *(const float4*)(base + 3 * HW + p);

    float dv[4] = {d4.x, d4.y, d4.z, d4.w};
    int   lin[4];
    bool  valid[4];
    bool  any = false;
    float yb = (float)h - 256.0f;    // fx=fy=256, cx=cy=256

    #pragma unroll
    for (int k = 0; k < 4; k++) {
        float d = dv[k];
        bool ok = (d > 0.0f) && (d < 10.0f) && isfinite(d);
        float x = ((float)(w0 + k) - 256.0f) * d * (1.0f / 256.0f);
        float y = yb * d * (1.0f / 256.0f);
        // rintf = round-half-even = jnp.round; 15.75 == 63/4 exactly, same
        // single rounding as ((p+2)/4)*63 in the reference.
        float fx_ = rintf((x + 2.0f) * 15.75f);
        float fy_ = rintf((y + 2.0f) * 15.75f);
        float fz_ = rintf((d + 2.0f) * 15.75f);
        ok = ok && (fx_ >= 0.0f) && (fx_ <= 63.0f)
                && (fy_ >= 0.0f) && (fy_ <= 63.0f)
                && (fz_ >= 32.0f) && (fz_ <= 63.0f);
        valid[k] = ok;
        any = any || ok;
        int cx = (int)fx_, cy = (int)fy_, cz = (int)fz_;
        lin[k] = ((((b << 6) + cx) << 6) | cy) << 5 | (cz - 32);
    }

    if (!any) return;

    float4 r4 = *(const float4*)(base + 0 * HW + p);
    float4 g4 = *(const float4*)(base + 1 * HW + p);
    float4 b4 = *(const float4*)(base + 2 * HW + p);
    float rv[4] = {r4.x, r4.y, r4.z, r4.w};
    float gv[4] = {g4.x, g4.y, g4.z, g4.w};
    float bv[4] = {b4.x, b4.y, b4.z, b4.w};

    #pragma unroll
    for (int k = 0; k < 4; k++) {
        if (valid[k]) {
            float* a = (float*)&g_acc[lin[k]];
            asm volatile(
                "red.global.add.v4.f32 [%0], {%1, %2, %3, %4};"
                :: "l"(a), "f"(1.0f), "f"(rv[k]), "f"(gv[k]), "f"(bv[k])
                : "memory");
        }
    }
}

// Branch-free per-voxel resolve: when count==0 sums are exactly 0, so
// sum * rcp(max(count,1)) == 0 without any guard.
__device__ __forceinline__ void resolve(float4 a, float& occ, float& r,
                                        float& g, float& b) {
    float inv = __frcp_rn(fmaxf(a.x, 1.0f));  // single MUFU.RCP
    occ = (a.x > 0.0f) ? 1.0f : 0.0f;         // FSETP + SEL
    r = a.y * inv;
    g = a.z * inv;
    b = a.w * inv;
}

// Uniform-warp finalize: thread t owns 4 contiguous scratch entries
// (cz in [32,64)) and also writes the matching zero-half (cz in [0,32))
// float4 for all 4 channels. No divergence; all accesses 128B-coalesced.
__global__ void finalize_kernel(float* __restrict__ out) {
    int t = blockIdx.x * blockDim.x + threadIdx.x;
    if (t >= NSCRATCH / 4) return;
    int s = t << 2;                    // 4 contiguous scratch entries
    int b = s >> 17;                   // / SCR_PER_B
    int sl = s & (SCR_PER_B - 1);      // local: ((cx*64+cy)*32 + (cz-32))

    float4 a0 = g_acc[s + 0];
    float4 a1 = g_acc[s + 1];
    float4 a2 = g_acc[s + 2];
    float4 a3 = g_acc[s + 3];

    // Re-zero scratch for the next graph replay.
    float4 z = make_float4(0.f, 0.f, 0.f, 0.f);
    g_acc[s + 0] = z; g_acc[s + 1] = z; g_acc[s + 2] = z; g_acc[s + 3] = z;

    float4 occ, rr, gg, bb;
    resolve(a0, occ.x, rr.x, gg.x, bb.x);
    resolve(a1, occ.y, rr.y, gg.y, bb.y);
    resolve(a2, occ.z, rr.z, gg.z, bb.z);
    resolve(a3, occ.w, rr.w, gg.w, bb.w);

    // out voxel offset: r = (cx*64+cy)*64 + cz ; here cz = (sl&31)+32.
    int rhi = (sl >> 5) << 6;          // (cx*64+cy)*64
    int rocc = rhi + (sl & 31) + 32;   // occupied half (s&31 multiple of 4)
    int rzer = rhi + (sl & 31);        // zero half, same alignment

    float* ob = out + (size_t)b * (4 * V3);

    *(float4*)(ob + rocc)          = occ;
    *(float4*)(ob + V3 + rocc)     = rr;
    *(float4*)(ob + 2 * V3 + rocc) = gg;
    *(float4*)(ob + 3 * V3 + rocc) = bb;

    *(float4*)(ob + rzer)          = z;
    *(float4*)(ob + V3 + rzer)     = z;
    *(float4*)(ob + 2 * V3 + rzer) = z;
    *(float4*)(ob + 3 * V3 + rzer) = z;
}

extern "C" void kernel_launch(void* const* d_in, const int* in_sizes, int n_in,
                              void* d_out, int out_size) {
    const float* rgbd = (const float*)d_in[0];
    float* out = (float*)d_out;

    const int T = 256;
    splat_kernel<<<(NPIX / 4 + T - 1) / T, T>>>(rgbd);
    finalize_kernel<<<(NSCRATCH / 4 + T - 1) / T, T>>>(out);
}

// round 4
// speedup vs baseline: 1.9129x; 1.2035x over previous
#include <cuda_runtime.h>
#include <math.h>
#include <stdint.h>

// Problem constants (fixed by setup_inputs)
#define HH 512
#define WW 512
#define HW (HH * WW)          // 262144
#define NPIX (32 * HW)        // 8388608
#define VV 64
#define V3 (VV * VV * VV)     // 262144
#define NVOX (32 * V3)        // 8388608

// Reachability: d>0 && coords in range forces cz = rint((d+2)*15.75) in
// [32,63]. Scratch: [((b*64+cx)*64+cy)*32 + (cz-32)] float4{count,r,g,b}.
// 64 MB total -> fits L2 (126 MB). We pin it with L2::evict_last policies
// and stream input/output with L2::evict_first so scratch never round-trips
// to DRAM (atomics, finalize read, rezero, next replay's atomics all hit L2).
#define NSCRATCH (NVOX / 2)        // 4194304 entries * 16B = 64 MB
#define SCR_PER_B (VV * VV * 32)   // 131072

__device__ float4 g_acc[NSCRATCH];   // zero-init at load; finalize re-zeros.

__device__ __forceinline__ uint64_t pol_evict_last() {
    uint64_t p;
    asm("createpolicy.fractional.L2::evict_last.b64 %0, 1.0;" : "=l"(p));
    return p;
}
__device__ __forceinline__ uint64_t pol_evict_first() {
    uint64_t p;
    asm("createpolicy.fractional.L2::evict_first.b64 %0, 1.0;" : "=l"(p));
    return p;
}

__device__ __forceinline__ float4 ldg_stream(const float* a, uint64_t pol) {
    float4 v;
    asm("ld.global.nc.L2::cache_hint.v4.f32 {%0,%1,%2,%3}, [%4], %5;"
        : "=f"(v.x), "=f"(v.y), "=f"(v.z), "=f"(v.w)
        : "l"(a), "l"(pol));
    return v;
}
__device__ __forceinline__ void stg_stream(float* a, float4 v, uint64_t pol) {
    asm volatile("st.global.L2::cache_hint.v4.f32 [%0], {%1,%2,%3,%4}, %5;"
                 :: "l"(a), "f"(v.x), "f"(v.y), "f"(v.z), "f"(v.w), "l"(pol)
                 : "memory");
}
__device__ __forceinline__ float4 ldg_keep(const float4* a, uint64_t pol) {
    float4 v;
    asm("ld.global.L2::cache_hint.v4.f32 {%0,%1,%2,%3}, [%4], %5;"
        : "=f"(v.x), "=f"(v.y), "=f"(v.z), "=f"(v.w)
        : "l"(a), "l"(pol));
    return v;
}
__device__ __forceinline__ void stg_keep(float4* a, float4 v, uint64_t pol) {
    asm volatile("st.global.L2::cache_hint.v4.f32 [%0], {%1,%2,%3,%4}, %5;"
                 :: "l"(a), "f"(v.x), "f"(v.y), "f"(v.z), "f"(v.w), "l"(pol)
                 : "memory");
}

__global__ __launch_bounds__(256) void splat_kernel(const float* __restrict__ rgbd) {
    int t = blockIdx.x * blockDim.x + threadIdx.x;
    if (t >= NPIX / 4) return;
    uint64_t pfirst = pol_evict_first();
    uint64_t plast  = pol_evict_last();

    int idx = t << 2;                // first of 4 consecutive pixels
    int b = idx >> 18;               // / HW
    int p = idx & (HW - 1);          // % HW   (multiple of 4)
    int h = p >> 9;                  // row (same for all 4: 512 % 4 == 0)
    int w0 = p & (WW - 1);

    const float* base = rgbd + (size_t)b * (4 * HW);
    float4 d4 = ldg_stream(base + 3 * HW + p, pfirst);

    float dv[4] = {d4.x, d4.y, d4.z, d4.w};
    int   lin[4];
    bool  valid[4];
    bool  any = false;
    float yb = (float)h - 256.0f;    // fx=fy=256, cx=cy=256

    #pragma unroll
    for (int k = 0; k < 4; k++) {
        float d = dv[k];
        bool ok = (d > 0.0f) && (d < 10.0f) && isfinite(d);
        float x = ((float)(w0 + k) - 256.0f) * d * (1.0f / 256.0f);
        float y = yb * d * (1.0f / 256.0f);
        // rintf = round-half-even = jnp.round; 15.75 == 63/4 exactly, same
        // single rounding as ((p+2)/4)*63 in the reference.
        float fx_ = rintf((x + 2.0f) * 15.75f);
        float fy_ = rintf((y + 2.0f) * 15.75f);
        float fz_ = rintf((d + 2.0f) * 15.75f);
        ok = ok && (fx_ >= 0.0f) && (fx_ <= 63.0f)
                && (fy_ >= 0.0f) && (fy_ <= 63.0f)
                && (fz_ >= 32.0f) && (fz_ <= 63.0f);
        valid[k] = ok;
        any = any || ok;
        int cx = (int)fx_, cy = (int)fy_, cz = (int)fz_;
        lin[k] = ((((b << 6) + cx) << 6) | cy) << 5 | (cz - 32);
    }

    if (!any) return;

    float4 r4 = ldg_stream(base + 0 * HW + p, pfirst);
    float4 g4 = ldg_stream(base + 1 * HW + p, pfirst);
    float4 b4 = ldg_stream(base + 2 * HW + p, pfirst);
    float rv[4] = {r4.x, r4.y, r4.z, r4.w};
    float gv[4] = {g4.x, g4.y, g4.z, g4.w};
    float bv[4] = {b4.x, b4.y, b4.z, b4.w};

    #pragma unroll
    for (int k = 0; k < 4; k++) {
        if (valid[k]) {
            float* a = (float*)&g_acc[lin[k]];
            // 128-bit vector reduction, scratch pinned via evict_last.
            asm volatile(
                "red.global.add.L2::cache_hint.v4.f32 [%0], {%1,%2,%3,%4}, %5;"
                :: "l"(a), "f"(1.0f), "f"(rv[k]), "f"(gv[k]), "f"(bv[k]),
                   "l"(plast)
                : "memory");
        }
    }
}

// Branch-free resolve: count==0 => sums exactly 0 => sum*rcp(max(count,1))==0.
__device__ __forceinline__ void resolve(float4 a, float& occ, float& r,
                                        float& g, float& b) {
    float inv = __frcp_rn(fmaxf(a.x, 1.0f));
    occ = (a.x > 0.0f) ? 1.0f : 0.0f;
    r = a.y * inv;
    g = a.z * inv;
    b = a.w * inv;
}

__global__ __launch_bounds__(256) void finalize_kernel(float* __restrict__ out) {
    int t = blockIdx.x * blockDim.x + threadIdx.x;
    if (t >= NSCRATCH / 4) return;
    uint64_t pfirst = pol_evict_first();
    uint64_t plast  = pol_evict_last();

    int s = t << 2;                    // 4 contiguous scratch entries
    int b = s >> 17;                   // / SCR_PER_B
    int sl = s & (SCR_PER_B - 1);      // local: ((cx*64+cy)*32 + (cz-32))

    float4 a0 = ldg_keep(&g_acc[s + 0], plast);
    float4 a1 = ldg_keep(&g_acc[s + 1], plast);
    float4 a2 = ldg_keep(&g_acc[s + 2], plast);
    float4 a3 = ldg_keep(&g_acc[s + 3], plast);

    // Re-zero scratch for the next graph replay (stays in L2).
    float4 z = make_float4(0.f, 0.f, 0.f, 0.f);
    stg_keep(&g_acc[s + 0], z, plast);
    stg_keep(&g_acc[s + 1], z, plast);
    stg_keep(&g_acc[s + 2], z, plast);
    stg_keep(&g_acc[s + 3], z, plast);

    float4 occ, rr, gg, bb;
    resolve(a0, occ.x, rr.x, gg.x, bb.x);
    resolve(a1, occ.y, rr.y, gg.y, bb.y);
    resolve(a2, occ.z, rr.z, gg.z, bb.z);
    resolve(a3, occ.w, rr.w, gg.w, bb.w);

    // out voxel offset: r = (cx*64+cy)*64 + cz ; here cz = (sl&31)+32.
    int rhi = (sl >> 5) << 6;          // (cx*64+cy)*64
    int rocc = rhi + (sl & 31) + 32;   // occupied half
    int rzer = rhi + (sl & 31);        // zero half

    float* ob = out + (size_t)b * (4 * V3);

    stg_stream(ob + rocc,          occ, pfirst);
    stg_stream(ob + V3 + rocc,     rr,  pfirst);
    stg_stream(ob + 2 * V3 + rocc, gg,  pfirst);
    stg_stream(ob + 3 * V3 + rocc, bb,  pfirst);

    stg_stream(ob + rzer,          z, pfirst);
    stg_stream(ob + V3 + rzer,     z, pfirst);
    stg_stream(ob + 2 * V3 + rzer, z, pfirst);
    stg_stream(ob + 3 * V3 + rzer, z, pfirst);
}

extern "C" void kernel_launch(void* const* d_in, const int* in_sizes, int n_in,
                              void* d_out, int out_size) {
    const float* rgbd = (const float*)d_in[0];
    float* out = (float*)d_out;

    const int T = 256;
    splat_kernel<<<(NPIX / 4 + T - 1) / T, T>>>(rgbd);
    finalize_kernel<<<(NSCRATCH / 4 + T - 1) / T, T>>>(out);
}

// round 5
// speedup vs baseline: 2.6193x; 1.3693x over previous
#include <cuda_runtime.h>
#include <math.h>
#include <stdint.h>

// Problem constants (fixed by setup_inputs)
#define HH 512
#define WW 512
#define HW (HH * WW)          // 262144
#define NPIX (32 * HW)        // 8388608
#define VV 64
#define V3 (VV * VV * VV)     // 262144
#define NVOX (32 * V3)        // 8388608

// Reachability: d>0 && coords in range forces cz = rint((d+2)*15.75) in
// [32,63]. Scratch: [((b*64+cx)*64+cy)*32 + (cz-32)] float4{count,r,g,b}.
// 64 MB. Lifecycle per call: zero_kernel writes it (dirty in L2, no DRAM
// read), splat atomics hit L2, finalize reads it and DISCARDs the lines
// (discard.global.L2 = invalidate without writeback) -> scratch ideally
// never touches DRAM.
#define NSCRATCH (NVOX / 2)        // 4194304 entries * 16B = 64 MB
#define SCR_PER_B (VV * VV * 32)   // 131072

__device__ __align__(128) float4 g_acc[NSCRATCH];

__device__ __forceinline__ uint64_t pol_evict_first() {
    uint64_t p;
    asm("createpolicy.fractional.L2::evict_first.b64 %0, 1.0;" : "=l"(p));
    return p;
}

__device__ __forceinline__ float4 ldg_stream(const float* a, uint64_t pol) {
    float4 v;
    asm("ld.global.nc.L2::cache_hint.v4.f32 {%0,%1,%2,%3}, [%4], %5;"
        : "=f"(v.x), "=f"(v.y), "=f"(v.z), "=f"(v.w)
        : "l"(a), "l"(pol));
    return v;
}
__device__ __forceinline__ void stg_stream(float* a, float4 v, uint64_t pol) {
    asm volatile("st.global.L2::cache_hint.v4.f32 [%0], {%1,%2,%3,%4}, %5;"
                 :: "l"(a), "f"(v.x), "f"(v.y), "f"(v.z), "f"(v.w), "l"(pol)
                 : "memory");
}

// ---------------------------------------------------------------- zero ----
__global__ __launch_bounds__(256) void zero_kernel() {
    int t = blockIdx.x * blockDim.x + threadIdx.x;
    int s = t << 2;                       // 4 float4 = 64B per thread
    if (s >= NSCRATCH) return;
    float4 z = make_float4(0.f, 0.f, 0.f, 0.f);
    g_acc[s + 0] = z;
    g_acc[s + 1] = z;
    g_acc[s + 2] = z;
    g_acc[s + 3] = z;
}

// --------------------------------------------------------------- splat ----
__global__ __launch_bounds__(256) void splat_kernel(const float* __restrict__ rgbd) {
    int t = blockIdx.x * blockDim.x + threadIdx.x;
    if (t >= NPIX / 4) return;
    uint64_t pfirst = pol_evict_first();

    int idx = t << 2;                // first of 4 consecutive pixels
    int b = idx >> 18;               // / HW
    int p = idx & (HW - 1);          // % HW   (multiple of 4)
    int h = p >> 9;                  // row (same for all 4: 512 % 4 == 0)
    int w0 = p & (WW - 1);

    const float* base = rgbd + (size_t)b * (4 * HW);
    float4 d4 = ldg_stream(base + 3 * HW + p, pfirst);

    float dv[4] = {d4.x, d4.y, d4.z, d4.w};
    int   lin[4];
    bool  valid[4];
    bool  any = false;
    float yb = (float)h - 256.0f;    // fx=fy=256, cx=cy=256

    #pragma unroll
    for (int k = 0; k < 4; k++) {
        float d = dv[k];
        bool ok = (d > 0.0f) && (d < 10.0f) && isfinite(d);
        float x = ((float)(w0 + k) - 256.0f) * d * (1.0f / 256.0f);
        float y = yb * d * (1.0f / 256.0f);
        // rintf = round-half-even = jnp.round; 15.75 == 63/4 exactly, same
        // single rounding as ((p+2)/4)*63 in the reference.
        float fx_ = rintf((x + 2.0f) * 15.75f);
        float fy_ = rintf((y + 2.0f) * 15.75f);
        float fz_ = rintf((d + 2.0f) * 15.75f);
        ok = ok && (fx_ >= 0.0f) && (fx_ <= 63.0f)
                && (fy_ >= 0.0f) && (fy_ <= 63.0f)
                && (fz_ >= 32.0f) && (fz_ <= 63.0f);
        valid[k] = ok;
        any = any || ok;
        int cx = (int)fx_, cy = (int)fy_, cz = (int)fz_;
        lin[k] = ((((b << 6) + cx) << 6) | cy) << 5 | (cz - 32);
    }

    if (!any) return;

    float4 r4 = ldg_stream(base + 0 * HW + p, pfirst);
    float4 g4 = ldg_stream(base + 1 * HW + p, pfirst);
    float4 b4 = ldg_stream(base + 2 * HW + p, pfirst);
    float rv[4] = {r4.x, r4.y, r4.z, r4.w};
    float gv[4] = {g4.x, g4.y, g4.z, g4.w};
    float bv[4] = {b4.x, b4.y, b4.z, b4.w};

    #pragma unroll
    for (int k = 0; k < 4; k++) {
        if (valid[k]) {
            float* a = (float*)&g_acc[lin[k]];
            asm volatile(
                "red.global.add.v4.f32 [%0], {%1,%2,%3,%4};"
                :: "l"(a), "f"(1.0f), "f"(rv[k]), "f"(gv[k]), "f"(bv[k])
                : "memory");
        }
    }
}

// ------------------------------------------------------------ finalize ----
// Branch-free resolve: count==0 => sums exactly 0 => sum*rcp(max(count,1))==0.
// rcp.approx (MUFU.RCP, ~2^-22 rel err) is far inside the 1e-3 tolerance.
__device__ __forceinline__ void resolve(float4 a, float& occ, float& r,
                                        float& g, float& b) {
    float inv;
    asm("rcp.approx.f32 %0, %1;" : "=f"(inv) : "f"(fmaxf(a.x, 1.0f)));
    occ = (a.x > 0.0f) ? 1.0f : 0.0f;
    r = a.y * inv;
    g = a.z * inv;
    b = a.w * inv;
}

// Thread t owns ONE 128B scratch line = 8 entries (cz-32 in [sl&31, +8)),
// resolves them, writes occupied-half + zero-half output, then discards its
// scratch line from L2 (no writeback; next call's zero_kernel rewrites it).
__global__ __launch_bounds__(256) void finalize_kernel(float* __restrict__ out) {
    int t = blockIdx.x * blockDim.x + threadIdx.x;
    if (t >= NSCRATCH / 8) return;
    uint64_t pfirst = pol_evict_first();

    int s = t << 3;                    // 8 contiguous scratch entries (128B)
    int b = s >> 17;                   // / SCR_PER_B
    int sl = s & (SCR_PER_B - 1);      // ((cx*64+cy)*32 + (cz-32)), mult of 8

    float4 a[8];
    #pragma unroll
    for (int k = 0; k < 8; k++) a[k] = g_acc[s + k];

    float4 occ0, rr0, gg0, bb0, occ1, rr1, gg1, bb1;
    resolve(a[0], occ0.x, rr0.x, gg0.x, bb0.x);
    resolve(a[1], occ0.y, rr0.y, gg0.y, bb0.y);
    resolve(a[2], occ0.z, rr0.z, gg0.z, bb0.z);
    resolve(a[3], occ0.w, rr0.w, gg0.w, bb0.w);
    resolve(a[4], occ1.x, rr1.x, gg1.x, bb1.x);
    resolve(a[5], occ1.y, rr1.y, gg1.y, bb1.y);
    resolve(a[6], occ1.z, rr1.z, gg1.z, bb1.z);
    resolve(a[7], occ1.w, rr1.w, gg1.w, bb1.w);

    // out voxel offset: r = (cx*64+cy)*64 + cz ; here cz = (sl&31)+32.
    int rhi = (sl >> 5) << 6;          // (cx*64+cy)*64
    int rocc = rhi + (sl & 31) + 32;   // occupied half (16B aligned)
    int rzer = rhi + (sl & 31);        // zero half

    float* ob = out + (size_t)b * (4 * V3);
    float4 z = make_float4(0.f, 0.f, 0.f, 0.f);

    stg_stream(ob + rocc,              occ0, pfirst);
    stg_stream(ob + rocc + 4,          occ1, pfirst);
    stg_stream(ob + V3 + rocc,         rr0,  pfirst);
    stg_stream(ob + V3 + rocc + 4,     rr1,  pfirst);
    stg_stream(ob + 2 * V3 + rocc,     gg0,  pfirst);
    stg_stream(ob + 2 * V3 + rocc + 4, gg1,  pfirst);
    stg_stream(ob + 3 * V3 + rocc,     bb0,  pfirst);
    stg_stream(ob + 3 * V3 + rocc + 4, bb1,  pfirst);

    #pragma unroll
    for (int ch = 0; ch < 4; ch++) {
        stg_stream(ob + ch * V3 + rzer,     z, pfirst);
        stg_stream(ob + ch * V3 + rzer + 4, z, pfirst);
    }

    // Drop this thread's dirty scratch line without writeback. The occupied-
    // half stores above consumed the loaded values, so (in-order warp issue)
    // the line's data is secured before the discard issues.
    asm volatile("discard.global.L2 [%0], 128;" :: "l"(&g_acc[s]) : "memory");
}

extern "C" void kernel_launch(void* const* d_in, const int* in_sizes, int n_in,
                              void* d_out, int out_size) {
    const float* rgbd = (const float*)d_in[0];
    float* out = (float*)d_out;

    const int T = 256;
    zero_kernel<<<(NSCRATCH / 4 + T - 1) / T, T>>>();
    splat_kernel<<<(NPIX / 4 + T - 1) / T, T>>>(rgbd);
    finalize_kernel<<<(NSCRATCH / 8 + T - 1) / T, T>>>(out);
}